// round 3
// baseline (speedup 1.0000x reference)
#include <cuda_runtime.h>
#include <cuda_bf16.h>

// LSTM decoder, B=1024, S=256, H=128, O=7, T=512.
//  - gates = h @ (W_ih + W_hh).T + (b_ih + b_hh)   (both matmuls use h!)
//  - recurrence independent across batch -> persistent kernel, no global sync.
//
// 128 CTAs x 256 threads; CTA owns 8 batch rows.
// Thread mapping (L1TEX-optimal G=2,R=8): thread (hidx, half) computes TWO
// gates for hidden unit hidx across ALL 8 batch rows:
//   half 0 (warps 0-3): gates i,f   (weights in SMEM)
//   half 1 (warps 4-7): gate  g     (SMEM) + gate o (streamed from L2)
// h tile reads are warp-uniform broadcasts (1 wavefront each). Pointwise
// c/h update: halves exchange their 2 gates for the 4 rows the other half
// updates via an SMEM buffer (half0 updates rows 0-3, half1 rows 4-7).
// Inner products use packed fma.rn.f32x2 (2 fp32 FMA / instr).

#define B_   1024
#define S_   256
#define H_   128
#define O_   7

// combined weights in [gate][k4][hidx][kk] layout (k packed in float4)
__device__ float g_Wc[4 * 32 * 128 * 4];
__device__ float g_bc[512];

__global__ void prep_kernel(const float* __restrict__ Wih,
                            const float* __restrict__ Whh,
                            const float* __restrict__ bih,
                            const float* __restrict__ bhh) {
    int idx = blockIdx.x * blockDim.x + threadIdx.x;  // over 512*128
    if (idx < 512 * 128) {
        int j = idx >> 7;        // gate-row 0..511
        int k = idx & 127;       // input hidden idx
        float w = Wih[idx] + Whh[idx];
        int g = j >> 7;
        int h = j & 127;
        g_Wc[(((g * 32) + (k >> 2)) * 128 + h) * 4 + (k & 3)] = w;
    }
    if (idx < 512) g_bc[idx] = bih[idx] + bhh[idx];
}

__device__ __forceinline__ void fma2(unsigned long long& d,
                                     unsigned long long a,
                                     unsigned long long b) {
    asm("fma.rn.f32x2 %0, %1, %2, %0;" : "+l"(d) : "l"(a), "l"(b));
}

__device__ __forceinline__ float redu(unsigned long long v) {
    float2 f = *reinterpret_cast<float2*>(&v);
    return f.x + f.y;
}

__device__ __forceinline__ float sigf(float x) {
    // 1/(1+e^-x): safe at both extremes
    return __fdividef(1.0f, 1.0f + __expf(-x));
}

__device__ __forceinline__ float tanhf_fast(float x) {
    // 1 - 2/(e^{2x}+1): safe at both extremes
    return 1.0f - __fdividef(2.0f, __expf(2.0f * x) + 1.0f);
}

// dynamic smem layout (floats):
//   sW  : 3*32*128*4 = 49152  (gates i,f,g in [g][k4][hidx][kk])
//   sh  : 2*8*132    = 2112   (double-buffered h, padded stride 132)
//   sx0 : 4*128*2    = 1024   (half0 -> half1: i,f for rows 4..7, float2)
//   sx1 : 4*128*2    = 1024   (half1 -> half0: g,o for rows 0..3, float2)
#define SW_FLOATS  49152
#define SH_FLOATS  2112
#define SX_FLOATS  1024
#define SMEM_FLOATS (SW_FLOATS + SH_FLOATS + 2 * SX_FLOATS)

// gate inner-product body over one k4 chunk (8 rows, 2 gates)
#define GATE_K4(WA, WB)                                                    \
    {                                                                      \
        ulonglong2 h4[8];                                                  \
        _Pragma("unroll")                                                  \
        for (int r = 0; r < 8; r++)                                        \
            h4[r] = *reinterpret_cast<const ulonglong2*>(                  \
                hb + r * 132 + k4 * 4);                                    \
        ulonglong2 wa = (WA);                                              \
        ulonglong2 wb = (WB);                                              \
        _Pragma("unroll")                                                  \
        for (int r = 0; r < 8; r++) {                                      \
            fma2(acc0[r], wa.x, h4[r].x);                                  \
            fma2(acc0[r], wa.y, h4[r].y);                                  \
            fma2(acc1[r], wb.x, h4[r].x);                                  \
            fma2(acc1[r], wb.y, h4[r].y);                                  \
        }                                                                  \
    }

__global__ void __launch_bounds__(256, 1)
lstm_kernel(const float* __restrict__ ctx,
            const float* __restrict__ Wout,
            const float* __restrict__ bout,
            int T,
            float* __restrict__ out) {
    extern __shared__ float smem[];
    float*  sW  = smem;
    float*  sh  = smem + SW_FLOATS;
    float2* sx0 = reinterpret_cast<float2*>(smem + SW_FLOATS + SH_FLOATS);
    float2* sx1 = sx0 + 512;

    const int tid   = threadIdx.x;
    const int hidx  = tid & 127;
    const int ghalf = tid >> 7;       // 0: gates i,f   1: gates g,o
    const int r0    = blockIdx.x * 8; // global batch row base

    // stage weights for gates 0..2 into SMEM (float4 copy)
    {
        const float4* src = reinterpret_cast<const float4*>(g_Wc);
        float4* dst = reinterpret_cast<float4*>(sW);
        for (int i = tid; i < 3 * 32 * 128; i += 256) dst[i] = src[i];
    }

    // h0 = context_seq[:, S-1, :]
    for (int i = tid; i < 8 * 128; i += 256) {
        int r = i >> 7, k = i & 127;
        sh[(0 * 8 + r) * 132 + k] =
            ctx[((size_t)(r0 + r) * S_ + (S_ - 1)) * H_ + k];
    }

    // projection thread setup: tid<224 -> (row pr, out po, k-part ppart).
    // W_out slice cached in registers (t-invariant), interleaved k = part+4m.
    int pr = 0, po = 0, ppart = 0;
    float pbo = 0.f;
    float wc[32];
    if (tid < 224) {
        pr = tid / 28;
        int j = tid - pr * 28;
        po = j >> 2;
        ppart = j & 3;
        pbo = bout[po];
        #pragma unroll
        for (int m = 0; m < 32; m++)
            wc[m] = Wout[po * 128 + ppart + 4 * m];
    }

    // this thread's two gate biases
    const float biasA = g_bc[(ghalf ? 256 : 0)   + hidx]; // i or g
    const float biasB = g_bc[(ghalf ? 384 : 128) + hidx]; // f or o
    float cc[4] = {0.f, 0.f, 0.f, 0.f};  // c-state: half0 rows0-3, half1 rows4-7

    __syncthreads();

    const ulonglong2* sWp = reinterpret_cast<const ulonglong2*>(sW);
    const ulonglong2* gWo =
        reinterpret_cast<const ulonglong2*>(g_Wc + 3 * 32 * 128 * 4);

    int buf = 0;
    for (int t = 0; t < T; t++) {
        unsigned long long acc0[8], acc1[8];  // [row], packed f32x2
        #pragma unroll
        for (int r = 0; r < 8; r++) { acc0[r] = 0ull; acc1[r] = 0ull; }

        const float* hb = sh + buf * 8 * 132;

        if (ghalf == 0) {
            // gates i (0), f (1) from SMEM
            #pragma unroll 4
            for (int k4 = 0; k4 < 32; k4++)
                GATE_K4(sWp[(0 * 32 + k4) * 128 + hidx],
                        sWp[(1 * 32 + k4) * 128 + hidx]);
        } else {
            // gate g (2) from SMEM, gate o (3) streamed from L2
            #pragma unroll 4
            for (int k4 = 0; k4 < 32; k4++)
                GATE_K4(sWp[(2 * 32 + k4) * 128 + hidx],
                        gWo[k4 * 128 + hidx]);
        }

        // reduce + bias
        float gvA[8], gvB[8];
        #pragma unroll
        for (int r = 0; r < 8; r++) {
            gvA[r] = redu(acc0[r]) + biasA;
            gvB[r] = redu(acc1[r]) + biasB;
        }

        // exchange the 4 rows the other half updates
        if (ghalf == 0) {
            #pragma unroll
            for (int r = 4; r < 8; r++)
                sx0[(r - 4) * 128 + hidx] = make_float2(gvA[r], gvB[r]);
        } else {
            #pragma unroll
            for (int r = 0; r < 4; r++)
                sx1[r * 128 + hidx] = make_float2(gvA[r], gvB[r]);
        }
        __syncthreads();

        const int nbuf = buf ^ 1;
        if (ghalf == 0) {
            // update rows 0..3: own i,f; g,o from half1
            #pragma unroll
            for (int r = 0; r < 4; r++) {
                float2 go = sx1[r * 128 + hidx];
                float I  = sigf(gvA[r]);
                float F  = sigf(gvB[r]);
                float G  = tanhf_fast(go.x);
                float Ov = sigf(go.y);
                cc[r] = F * cc[r] + I * G;
                sh[(nbuf * 8 + r) * 132 + hidx] = Ov * tanhf_fast(cc[r]);
            }
        } else {
            // update rows 4..7: own g,o; i,f from half0
            #pragma unroll
            for (int r = 4; r < 8; r++) {
                float2 iff = sx0[(r - 4) * 128 + hidx];
                float I  = sigf(iff.x);
                float F  = sigf(iff.y);
                float G  = tanhf_fast(gvA[r]);
                float Ov = sigf(gvB[r]);
                cc[r - 4] = F * cc[r - 4] + I * G;
                sh[(nbuf * 8 + r) * 132 + hidx] = Ov * tanhf_fast(cc[r - 4]);
            }
        }
        __syncthreads();

        // output projection: 8 rows x 7 outs, 4-lane k-split (interleaved:
        // lane part reads k = part+4m -> conflict-free banks, W_out in regs)
        if (tid < 224) {
            const float* hr = sh + (nbuf * 8 + pr) * 132 + ppart;
            float s0 = 0.f, s1 = 0.f;
            #pragma unroll
            for (int m = 0; m < 32; m += 2) {
                s0 += hr[4 * m]     * wc[m];
                s1 += hr[4 * m + 4] * wc[m + 1];
            }
            float s = s0 + s1;
            s += __shfl_down_sync(0xffffffffu, s, 2);
            s += __shfl_down_sync(0xffffffffu, s, 1);
            if (ppart == 0)
                out[((size_t)(r0 + pr) * T + t) * O_ + po] = s + pbo;
        }
        buf = nbuf;
    }
}

extern "C" void kernel_launch(void* const* d_in, const int* in_sizes, int n_in,
                              void* d_out, int out_size) {
    const float* ctx  = (const float*)d_in[0];
    const float* Wih  = (const float*)d_in[1];
    const float* Whh  = (const float*)d_in[2];
    const float* bih  = (const float*)d_in[3];
    const float* bhh  = (const float*)d_in[4];
    const float* Wout = (const float*)d_in[5];
    const float* bout = (const float*)d_in[6];
    float* out = (float*)d_out;

    // T derived from output size (avoids prediction_len dtype ambiguity)
    int T = out_size / (B_ * O_);

    prep_kernel<<<256, 256>>>(Wih, Whh, bih, bhh);

    size_t smem_bytes = (size_t)SMEM_FLOATS * sizeof(float);
    cudaFuncSetAttribute(lstm_kernel,
                         cudaFuncAttributeMaxDynamicSharedMemorySize,
                         (int)smem_bytes);
    lstm_kernel<<<B_ / 8, 256, smem_bytes>>>(ctx, Wout, bout, T, out);
}